// round 5
// baseline (speedup 1.0000x reference)
#include <cuda_runtime.h>

// CTC greedy search — single kernel, last-block-per-column does the scan.
//   logits: (T=2048, N=32, V=1024) float32, batch_first = False
//   in_lens: (N,) int (int32 or int64 — detected at runtime)
// Output (float32): [ max_total (N) | paths (T*N, t*N+n) | out_lens (N) ]

#define T_DIM 2048
#define N_DIM 32
#define V_DIM 1024
#define BLANK 1023        // (-1 + V) % V
#define TPB 256
#define GRID_B ((T_DIM / 8) * N_DIM)   // 8192 blocks; b -> n = b>>8, t0 = (b&255)*8

// Scratch (allocation-free rule: __device__ globals; zero-init at load).
__device__ int   g_amax[(size_t)T_DIM * N_DIM];   // n-major
__device__ float g_maxv[(size_t)T_DIM * N_DIM];
__device__ int   g_done[N_DIM];

__global__ void __launch_bounds__(TPB, 4) ctc_all_kernel(
    const float* __restrict__ logits,
    const void* __restrict__ in_lens_raw,
    float* __restrict__ out)
{
    const int tid  = threadIdx.x;
    const int lane = tid & 31;
    const int wid  = tid >> 5;

    const int n = blockIdx.x >> 8;                 // batch column this block serves
    const int t = ((blockIdx.x & 255) << 3) + wid; // this warp's timestep

    float* out_paths = out + N_DIM;

    // =====================================================================
    // Phase 1: one warp per (t, n) row of V=1024 logits.
    // =====================================================================
    {
        const float4* row = reinterpret_cast<const float4*>(logits)
                          + ((size_t)t * N_DIM + n) * (V_DIM / 4);

        float4 v[8];
#pragma unroll
        for (int k = 0; k < 8; k++) v[k] = row[lane + 32 * k];

        // per-lane max + first-occurrence argmax
        float m = -1e30f; int mi = 0;
#pragma unroll
        for (int k = 0; k < 8; k++) {
            const int base = (lane + 32 * k) * 4;
            float x;
            x = v[k].x; if (x > m) { m = x; mi = base;     }
            x = v[k].y; if (x > m) { m = x; mi = base + 1; }
            x = v[k].z; if (x > m) { m = x; mi = base + 2; }
            x = v[k].w; if (x > m) { m = x; mi = base + 3; }
        }
#pragma unroll
        for (int off = 16; off; off >>= 1) {
            float om = __shfl_down_sync(0xffffffffu, m, off);
            int  omi = __shfl_down_sync(0xffffffffu, mi, off);
            if (om > m || (om == m && omi < mi)) { m = om; mi = omi; }
        }
        m  = __shfl_sync(0xffffffffu, m, 0);
        mi = __shfl_sync(0xffffffffu, mi, 0);

        float s = 0.f;
#pragma unroll
        for (int k = 0; k < 8; k++) {
            s += __expf(v[k].x - m) + __expf(v[k].y - m)
               + __expf(v[k].z - m) + __expf(v[k].w - m);
        }
#pragma unroll
        for (int off = 16; off; off >>= 1)
            s += __shfl_down_sync(0xffffffffu, s, off);

        if (lane == 0) {
            g_amax[n * T_DIM + t] = mi;
            g_maxv[n * T_DIM + t] = -logf(s);          // max over V of log_softmax
            out_paths[(size_t)t * N_DIM + n] = (float)mi;  // masked_scatter default
        }
    }

    // =====================================================================
    // Arrival: release writes, count this block's 8 rows into column n.
    // =====================================================================
    __shared__ int s_last;
    __threadfence();
    __syncthreads();
    if (tid == 0) {
        int old = atomicAdd(&g_done[n], 8);
        s_last = (old == T_DIM - 8);
    }
    __syncthreads();
    if (!s_last) return;

    // This block is the last finisher for column n — run the scan.
    __threadfence();   // acquire: make all column-n writes visible

    __shared__ int   swc[8];
    __shared__ float sws[8];

    // dtype-robust in_lens: values in [1,T]; int64 LE => high words are 0.
    const int* w32 = (const int*)in_lens_raw;
    const bool is64 = (w32[1] == 0);
    const int L = is64 ? (int)((const long long*)in_lens_raw)[n] : w32[n];

    const int*   a  = g_amax + n * T_DIM;
    const float* mv = g_maxv + n * T_DIM;

    const int t0 = tid * 8;
    const int4 A0 = reinterpret_cast<const int4*>(a)[2 * tid];
    const int4 A1 = reinterpret_cast<const int4*>(a)[2 * tid + 1];
    const float4 M0 = reinterpret_cast<const float4*>(mv)[2 * tid];
    const float4 M1 = reinterpret_cast<const float4*>(mv)[2 * tid + 1];

    int av[8] = {A0.x, A0.y, A0.z, A0.w, A1.x, A1.y, A1.z, A1.w};

    int prev = __shfl_up_sync(0xffffffffu, A1.w, 1);
    if (lane == 0) prev = (tid == 0) ? -123 : a[t0 - 1];

    bool kf[8]; int cnt = 0; int p = prev;
#pragma unroll
    for (int i = 0; i < 8; i++) {
        kf[i] = (av[i] != BLANK) && (av[i] != p) && (t0 + i < L);
        p = av[i];
        cnt += (int)kf[i];
    }

    float loc = 0.f;
    loc += (t0 + 0 < L) ? M0.x : 0.f;
    loc += (t0 + 1 < L) ? M0.y : 0.f;
    loc += (t0 + 2 < L) ? M0.z : 0.f;
    loc += (t0 + 3 < L) ? M0.w : 0.f;
    loc += (t0 + 4 < L) ? M1.x : 0.f;
    loc += (t0 + 5 < L) ? M1.y : 0.f;
    loc += (t0 + 6 < L) ? M1.z : 0.f;
    loc += (t0 + 7 < L) ? M1.w : 0.f;

    int inc = cnt;
#pragma unroll
    for (int off = 1; off < 32; off <<= 1) {
        int v = __shfl_up_sync(0xffffffffu, inc, off);
        if (lane >= off) inc += v;
        loc += __shfl_down_sync(0xffffffffu, loc, off);
    }
    if (lane == 31) swc[wid] = inc;
    if (lane == 0)  sws[wid] = loc;
    __syncthreads();

    if (wid == 0) {
        int v = (lane < 8) ? swc[lane] : 0;
        int inc2 = v;
#pragma unroll
        for (int off = 1; off < 32; off <<= 1) {
            int u = __shfl_up_sync(0xffffffffu, inc2, off);
            if (lane >= off) inc2 += u;
        }
        if (lane < 8) swc[lane] = inc2 - v;          // exclusive warp offsets
        if (lane == 7)
            out[N_DIM + (size_t)T_DIM * N_DIM + n] = (float)inc2;  // out_lens

        float fs = (lane < 8) ? sws[lane] : 0.f;
#pragma unroll
        for (int off = 16; off; off >>= 1)
            fs += __shfl_down_sync(0xffffffffu, fs, off);
        if (lane == 0) out[n] = fs;                  // max_total
    }
    __syncthreads();

    int pos = swc[wid] + (inc - cnt);
#pragma unroll
    for (int i = 0; i < 8; i++) {
        if (kf[i]) { out_paths[pos * N_DIM + n] = (float)av[i]; pos++; }
    }

    // Reset the column counter for deterministic graph replays.
    __syncthreads();
    if (tid == 0) atomicExch(&g_done[n], 0);
}

// ---------------------------------------------------------------------------
extern "C" void kernel_launch(void* const* d_in, const int* in_sizes, int n_in,
                              void* d_out, int out_size)
{
    const float* logits = (const float*)d_in[0];
    const void*  lens   = d_in[1];
    float* out = (float*)d_out;

    (void)in_sizes; (void)n_in; (void)out_size;

    ctc_all_kernel<<<GRID_B, TPB>>>(logits, lens, out);
}

// round 6
// speedup vs baseline: 1.0369x; 1.0369x over previous
#include <cuda_runtime.h>

// CTC greedy search — single kernel, last-block-per-column does the scan.
// Fences: ONE gpu-scope fence per block (tid0), not per-thread — per-thread
// __threadfence emits CCTL.IVALL (L1D flush) and tanked streaming BW in R3/R5.
//   logits: (T=2048, N=32, V=1024) float32, batch_first = False
//   in_lens: (N,) int (int32 or int64 — detected at runtime)
// Output (float32): [ max_total (N) | paths (T*N, t*N+n) | out_lens (N) ]

#define T_DIM 2048
#define N_DIM 32
#define V_DIM 1024
#define BLANK 1023        // (-1 + V) % V
#define TPB 256
#define GRID_B ((T_DIM / 8) * N_DIM)   // 8192 blocks; b -> n = b>>8, t = (b&255)*8+wid

// Scratch (allocation-free rule: __device__ globals; zero-init at load).
__device__ int   g_amax[(size_t)T_DIM * N_DIM];   // n-major
__device__ float g_maxv[(size_t)T_DIM * N_DIM];
__device__ int   g_done[N_DIM];

__global__ void __launch_bounds__(TPB, 4) ctc_all_kernel(
    const float* __restrict__ logits,
    const void* __restrict__ in_lens_raw,
    float* __restrict__ out)
{
    const int tid  = threadIdx.x;
    const int lane = tid & 31;
    const int wid  = tid >> 5;

    const int n = blockIdx.x >> 8;                 // batch column this block serves
    const int t = ((blockIdx.x & 255) << 3) + wid; // this warp's timestep

    float* out_paths = out + N_DIM;

    // =====================================================================
    // Phase 1: one warp per (t, n) row of V=1024 logits.
    // =====================================================================
    {
        const float4* row = reinterpret_cast<const float4*>(logits)
                          + ((size_t)t * N_DIM + n) * (V_DIM / 4);

        float4 v[8];
#pragma unroll
        for (int k = 0; k < 8; k++) v[k] = row[lane + 32 * k];

        // per-lane max + first-occurrence argmax
        float m = -1e30f; int mi = 0;
#pragma unroll
        for (int k = 0; k < 8; k++) {
            const int base = (lane + 32 * k) * 4;
            float x;
            x = v[k].x; if (x > m) { m = x; mi = base;     }
            x = v[k].y; if (x > m) { m = x; mi = base + 1; }
            x = v[k].z; if (x > m) { m = x; mi = base + 2; }
            x = v[k].w; if (x > m) { m = x; mi = base + 3; }
        }
#pragma unroll
        for (int off = 16; off; off >>= 1) {
            float om = __shfl_down_sync(0xffffffffu, m, off);
            int  omi = __shfl_down_sync(0xffffffffu, mi, off);
            if (om > m || (om == m && omi < mi)) { m = om; mi = omi; }
        }
        m  = __shfl_sync(0xffffffffu, m, 0);
        mi = __shfl_sync(0xffffffffu, mi, 0);

        float s = 0.f;
#pragma unroll
        for (int k = 0; k < 8; k++) {
            s += __expf(v[k].x - m) + __expf(v[k].y - m)
               + __expf(v[k].z - m) + __expf(v[k].w - m);
        }
#pragma unroll
        for (int off = 16; off; off >>= 1)
            s += __shfl_down_sync(0xffffffffu, s, off);

        if (lane == 0) {
            g_amax[n * T_DIM + t] = mi;
            g_maxv[n * T_DIM + t] = -logf(s);          // max over V of log_softmax
            out_paths[(size_t)t * N_DIM + n] = (float)mi;  // masked_scatter default
        }
    }

    // =====================================================================
    // Arrival: barrier (HB into tid0) -> tid0 fence (cumulative: publishes
    // all warps' writes) -> release atomic.
    // =====================================================================
    __shared__ int s_last;
    __syncthreads();
    if (tid == 0) {
        __threadfence();                       // ONE fence per block
        int old = atomicAdd(&g_done[n], 8);
        s_last = (old == T_DIM - 8);
        if (old == T_DIM - 8) __threadfence(); // acquire for the winner
    }
    __syncthreads();
    if (!s_last) return;

    // This block is the last finisher for column n — run the scan.
    __shared__ int   swc[8];
    __shared__ float sws[8];

    // dtype-robust in_lens: values in [1,T]; int64 LE => high words are 0.
    const int* w32 = (const int*)in_lens_raw;
    const bool is64 = (w32[1] == 0);
    const int L = is64 ? (int)((const long long*)in_lens_raw)[n] : w32[n];

    const int*   a  = g_amax + n * T_DIM;
    const float* mv = g_maxv + n * T_DIM;

    const int t0 = tid * 8;
    const int4 A0 = reinterpret_cast<const int4*>(a)[2 * tid];
    const int4 A1 = reinterpret_cast<const int4*>(a)[2 * tid + 1];
    const float4 M0 = reinterpret_cast<const float4*>(mv)[2 * tid];
    const float4 M1 = reinterpret_cast<const float4*>(mv)[2 * tid + 1];

    int av[8] = {A0.x, A0.y, A0.z, A0.w, A1.x, A1.y, A1.z, A1.w};

    int prev = __shfl_up_sync(0xffffffffu, A1.w, 1);
    if (lane == 0) prev = (tid == 0) ? -123 : a[t0 - 1];

    bool kf[8]; int cnt = 0; int p = prev;
#pragma unroll
    for (int i = 0; i < 8; i++) {
        kf[i] = (av[i] != BLANK) && (av[i] != p) && (t0 + i < L);
        p = av[i];
        cnt += (int)kf[i];
    }

    float loc = 0.f;
    loc += (t0 + 0 < L) ? M0.x : 0.f;
    loc += (t0 + 1 < L) ? M0.y : 0.f;
    loc += (t0 + 2 < L) ? M0.z : 0.f;
    loc += (t0 + 3 < L) ? M0.w : 0.f;
    loc += (t0 + 4 < L) ? M1.x : 0.f;
    loc += (t0 + 5 < L) ? M1.y : 0.f;
    loc += (t0 + 6 < L) ? M1.z : 0.f;
    loc += (t0 + 7 < L) ? M1.w : 0.f;

    int inc = cnt;
#pragma unroll
    for (int off = 1; off < 32; off <<= 1) {
        int v = __shfl_up_sync(0xffffffffu, inc, off);
        if (lane >= off) inc += v;
        loc += __shfl_down_sync(0xffffffffu, loc, off);
    }
    if (lane == 31) swc[wid] = inc;
    if (lane == 0)  sws[wid] = loc;
    __syncthreads();

    if (wid == 0) {
        int v = (lane < 8) ? swc[lane] : 0;
        int inc2 = v;
#pragma unroll
        for (int off = 1; off < 32; off <<= 1) {
            int u = __shfl_up_sync(0xffffffffu, inc2, off);
            if (lane >= off) inc2 += u;
        }
        if (lane < 8) swc[lane] = inc2 - v;          // exclusive warp offsets
        if (lane == 7)
            out[N_DIM + (size_t)T_DIM * N_DIM + n] = (float)inc2;  // out_lens

        float fs = (lane < 8) ? sws[lane] : 0.f;
#pragma unroll
        for (int off = 16; off; off >>= 1)
            fs += __shfl_down_sync(0xffffffffu, fs, off);
        if (lane == 0) out[n] = fs;                  // max_total
    }
    __syncthreads();

    int pos = swc[wid] + (inc - cnt);
#pragma unroll
    for (int i = 0; i < 8; i++) {
        if (kf[i]) { out_paths[pos * N_DIM + n] = (float)av[i]; pos++; }
    }

    // Reset the column counter for deterministic graph replays.
    __syncthreads();
    if (tid == 0) atomicExch(&g_done[n], 0);
}

// ---------------------------------------------------------------------------
extern "C" void kernel_launch(void* const* d_in, const int* in_sizes, int n_in,
                              void* d_out, int out_size)
{
    const float* logits = (const float*)d_in[0];
    const void*  lens   = d_in[1];
    float* out = (float*)d_out;

    (void)in_sizes; (void)n_in; (void)out_size;

    ctc_all_kernel<<<GRID_B, TPB>>>(logits, lens, out);
}